// round 1
// baseline (speedup 1.0000x reference)
#include <cuda_runtime.h>
#include <cuda_bf16.h>
#include <cstdint>

#define D_FEAT      64
#define N_NODES_MAX 100000
#define EPS         64            // edges per sub-chunk (sequential per thread-group)
#define SUBS        8             // sub-chunks per block
#define EPB         (EPS * SUBS)  // 512 edges per block
#define THREADS     128           // 16 feature-threads (float4) x 8 sub-chunks

// Scratch for intermediate hop result (allocation-free per harness rules).
__device__ float g_tmp[(size_t)N_NODES_MAX * D_FEAT];

__global__ void zero_kernel(float4* __restrict__ p, int n4) {
    int i = blockIdx.x * blockDim.x + threadIdx.x;
    if (i < n4) p[i] = make_float4(0.f, 0.f, 0.f, 0.f);
}

// One block processes EPB consecutive edges (rows sorted -> long same-row runs).
// Thread layout: tid = sub*16 + d4. Each 16-thread group walks EPS consecutive
// edges, each thread owning 4 features (float4). Register accumulation across
// same-row runs; atomicAdd flush on row change / group end.
__global__ void __launch_bounds__(THREADS)
spmm_kernel(const float* __restrict__ src,
            const int*   __restrict__ erow,
            const int*   __restrict__ ecol,
            const float* __restrict__ eval,
            float*       __restrict__ dst,
            int n_edges) {
    __shared__ int   s_row[EPB];
    __shared__ int   s_col[EPB];
    __shared__ float s_val[EPB];

    const int base = blockIdx.x * EPB;
    const int tid  = threadIdx.x;

    // Cooperative stage of edge triples into smem
    #pragma unroll
    for (int i = tid; i < EPB; i += THREADS) {
        int e = base + i;
        if (e < n_edges) {
            s_row[i] = erow[e];
            s_col[i] = ecol[e];
            s_val[i] = eval[e];
        } else {
            s_row[i] = -1;   // sentinel: no work
        }
    }
    __syncthreads();

    const int d4  = tid & 15;   // which float4 of the 64-wide feature row
    const int sub = tid >> 4;   // which sub-chunk of EPS edges
    const int off = sub * EPS;

    int cur = s_row[off];
    if (cur < 0) return;        // entire sub-chunk past the end

    float4 acc = make_float4(0.f, 0.f, 0.f, 0.f);

    #pragma unroll 4
    for (int i = 0; i < EPS; i++) {
        int r = s_row[off + i];
        if (r < 0) break;       // uniform within the 16-thread group
        if (r != cur) {
            float* p = dst + (size_t)cur * D_FEAT + d4 * 4;
            atomicAdd(p + 0, acc.x);
            atomicAdd(p + 1, acc.y);
            atomicAdd(p + 2, acc.z);
            atomicAdd(p + 3, acc.w);
            acc = make_float4(0.f, 0.f, 0.f, 0.f);
            cur = r;
        }
        const float4 xv = *reinterpret_cast<const float4*>(
            src + (size_t)s_col[off + i] * D_FEAT + d4 * 4);
        const float v = s_val[off + i];
        acc.x += v * xv.x;
        acc.y += v * xv.y;
        acc.z += v * xv.z;
        acc.w += v * xv.w;
    }

    float* p = dst + (size_t)cur * D_FEAT + d4 * 4;
    atomicAdd(p + 0, acc.x);
    atomicAdd(p + 1, acc.y);
    atomicAdd(p + 2, acc.z);
    atomicAdd(p + 3, acc.w);
}

extern "C" void kernel_launch(void* const* d_in, const int* in_sizes, int n_in,
                              void* d_out, int out_size) {
    const float* x    = (const float*)d_in[0];
    const int*   erow = (const int*)  d_in[1];
    const int*   ecol = (const int*)  d_in[2];
    const float* eval = (const float*)d_in[3];
    float*       out  = (float*)d_out;

    const int n_edges = in_sizes[1];
    const int n_elems = out_size;           // N_NODES * D_FEAT
    const int n4      = n_elems / 4;

    void* tmp_sym = nullptr;
    cudaGetSymbolAddress(&tmp_sym, g_tmp);
    float* tmp = (float*)tmp_sym;

    const int zgrid = (n4 + 255) / 256;
    const int sgrid = (n_edges + EPB - 1) / EPB;

    // Hop 1: tmp = A @ x
    zero_kernel<<<zgrid, 256>>>((float4*)tmp, n4);
    spmm_kernel<<<sgrid, THREADS>>>(x, erow, ecol, eval, tmp, n_edges);

    // Hop 2: out = A @ tmp
    zero_kernel<<<zgrid, 256>>>((float4*)out, n4);
    spmm_kernel<<<sgrid, THREADS>>>(tmp, erow, ecol, eval, out, n_edges);
}

// round 2
// speedup vs baseline: 1.3180x; 1.3180x over previous
#include <cuda_runtime.h>
#include <cuda_bf16.h>
#include <cstdint>

#define D_FEAT      64
#define N_NODES_MAX 100000
#define EPS         64            // edges per 16-thread group (sequential run-walk)
#define SUBS        8             // groups per block
#define EPB         (EPS * SUBS)  // 512 edges per block
#define THREADS     128

// Scratch for the intermediate hop (allocation-free per harness rules).
__device__ float g_tmp[(size_t)N_NODES_MAX * D_FEAT];

__device__ __forceinline__ void red_add_v4(float* p, float4 a) {
    asm volatile("red.global.add.v4.f32 [%0], {%1, %2, %3, %4};"
                 :: "l"(p), "f"(a.x), "f"(a.y), "f"(a.z), "f"(a.w)
                 : "memory");
}

__global__ void zero_kernel(float4* __restrict__ p, int n4) {
    int i = blockIdx.x * blockDim.x + threadIdx.x;
    if (i < n4) p[i] = make_float4(0.f, 0.f, 0.f, 0.f);
}

// Block = 512 sorted edges. tid = sub*16 + d4: 16 feature-threads (float4 each)
// walk EPS consecutive edges, accumulating in registers across same-row runs.
// Runs fully interior to a group are exclusively owned (rows sorted ->
// contiguous) and flushed with plain STG.128; boundary runs use red.add.v4.
__global__ void __launch_bounds__(THREADS)
spmm_kernel(const float* __restrict__ src,
            const int*   __restrict__ erow,
            const int*   __restrict__ ecol,
            const float* __restrict__ eval,
            float*       __restrict__ dst,
            int n_edges) {
    __shared__ alignas(16) int   s_row[EPB];
    __shared__ alignas(16) int   s_col[EPB];
    __shared__ alignas(16) float s_val[EPB];

    const int base = blockIdx.x * EPB;
    const int tid  = threadIdx.x;

    // Stage edge triples. Padding: repeat last valid row with val=0 (harmless
    // atomic-add of 0; never triggers the interior-STG path).
    #pragma unroll
    for (int i = tid; i < EPB; i += THREADS) {
        int e    = base + i;
        int esrc = min(e, n_edges - 1);
        int in   = (e < n_edges);
        s_row[i] = erow[esrc];
        s_col[i] = in ? ecol[esrc] : 0;
        s_val[i] = in ? eval[esrc] : 0.f;
    }
    __syncthreads();

    const int d4  = tid & 15;
    const int sub = tid >> 4;
    const int off = sub * EPS;
    const float* sp = src + d4 * 4;

    int    cur       = s_row[off];
    int    run_start = 0;           // loop index where current run began
    float4 acc       = make_float4(0.f, 0.f, 0.f, 0.f);

    #pragma unroll 2
    for (int ib = 0; ib < EPS; ib += 4) {
        // Vectorized edge reads (1 LDS.128 each, broadcast within group)
        const int4   r4 = *reinterpret_cast<const int4*>(s_row + off + ib);
        const int4   c4 = *reinterpret_cast<const int4*>(s_col + off + ib);
        const float4 v4 = *reinterpret_cast<const float4*>(s_val + off + ib);

        // Batch all 4 gathers up front (MLP=4+ per warp)
        const float4 g0 = *reinterpret_cast<const float4*>(sp + (size_t)c4.x * D_FEAT);
        const float4 g1 = *reinterpret_cast<const float4*>(sp + (size_t)c4.y * D_FEAT);
        const float4 g2 = *reinterpret_cast<const float4*>(sp + (size_t)c4.z * D_FEAT);
        const float4 g3 = *reinterpret_cast<const float4*>(sp + (size_t)c4.w * D_FEAT);

        #define STEP(R, V, G, IDX)                                           \
        do {                                                                 \
            if ((R) != cur) {                                                \
                float* p = dst + (size_t)cur * D_FEAT + d4 * 4;              \
                if (run_start > 0) {                                         \
                    *reinterpret_cast<float4*>(p) = acc;   /* exclusive */   \
                } else {                                                     \
                    red_add_v4(p, acc);                                      \
                }                                                            \
                acc = make_float4(0.f, 0.f, 0.f, 0.f);                       \
                cur = (R);                                                   \
                run_start = (IDX);                                           \
            }                                                                \
            acc.x += (V) * (G).x;                                            \
            acc.y += (V) * (G).y;                                            \
            acc.z += (V) * (G).z;                                            \
            acc.w += (V) * (G).w;                                            \
        } while (0)

        STEP(r4.x, v4.x, g0, ib + 0);
        STEP(r4.y, v4.y, g1, ib + 1);
        STEP(r4.z, v4.z, g2, ib + 2);
        STEP(r4.w, v4.w, g3, ib + 3);
        #undef STEP
    }

    // Final run may continue into the next group -> always atomic.
    red_add_v4(dst + (size_t)cur * D_FEAT + d4 * 4, acc);
}

extern "C" void kernel_launch(void* const* d_in, const int* in_sizes, int n_in,
                              void* d_out, int out_size) {
    const float* x    = (const float*)d_in[0];
    const int*   erow = (const int*)  d_in[1];
    const int*   ecol = (const int*)  d_in[2];
    const float* eval = (const float*)d_in[3];
    float*       out  = (float*)d_out;

    const int n_edges = in_sizes[1];
    const int n4      = out_size / 4;

    void* tmp_sym = nullptr;
    cudaGetSymbolAddress(&tmp_sym, g_tmp);
    float* tmp = (float*)tmp_sym;

    const int zgrid = (n4 + 255) / 256;
    const int sgrid = (n_edges + EPB - 1) / EPB;

    // Hop 1: tmp = A @ x
    zero_kernel<<<zgrid, 256>>>((float4*)tmp, n4);
    spmm_kernel<<<sgrid, THREADS>>>(x, erow, ecol, eval, tmp, n_edges);

    // Hop 2: out = A @ tmp
    zero_kernel<<<zgrid, 256>>>((float4*)out, n4);
    spmm_kernel<<<sgrid, THREADS>>>(tmp, erow, ecol, eval, out, n_edges);
}

// round 3
// speedup vs baseline: 1.5253x; 1.1573x over previous
#include <cuda_runtime.h>
#include <cuda_bf16.h>
#include <cstdint>

#define D_FEAT      64
#define ROW_BYTES   256           // D_FEAT * 4
#define N_NODES_MAX 100000
#define EPS         64            // edges per 16-thread group
#define SUBS        8             // groups per block
#define EPB         (EPS * SUBS)  // 512 edges per block
#define THREADS     128

// Scratch for the intermediate hop (allocation-free per harness rules).
__device__ float g_tmp[(size_t)N_NODES_MAX * D_FEAT];

__device__ __forceinline__ void red_add_v4(float* p, float4 a) {
    asm volatile("red.global.add.v4.f32 [%0], {%1, %2, %3, %4};"
                 :: "l"(p), "f"(a.x), "f"(a.y), "f"(a.z), "f"(a.w)
                 : "memory");
}

// Zero both hop buffers in one pass.
__global__ void zero2_kernel(float4* __restrict__ a, float4* __restrict__ b, int n4) {
    int i = blockIdx.x * blockDim.x + threadIdx.x;
    if (i < n4) {
        a[i] = make_float4(0.f, 0.f, 0.f, 0.f);
        b[i] = make_float4(0.f, 0.f, 0.f, 0.f);
    }
}

// Block = 512 sorted edges. tid = sub*16 + d4: 16 feature-threads (float4 each)
// walk EPS consecutive edges, accumulating in registers across same-row runs.
// Interior runs are exclusively owned (rows sorted) -> plain STG.128; boundary
// runs use red.add.v4. Inner loop batches 8 gathers for MLP=8.
__global__ void __launch_bounds__(THREADS)
spmm_kernel(const float* __restrict__ src,
            const int*   __restrict__ erow,
            const int*   __restrict__ ecol,
            const float* __restrict__ eval,
            float*       __restrict__ dst,
            int n_edges) {
    __shared__ alignas(16) int   s_row[EPB];
    __shared__ alignas(16) int   s_off[EPB];   // col * ROW_BYTES
    __shared__ alignas(16) float s_val[EPB];

    const int base = blockIdx.x * EPB;
    const int tid  = threadIdx.x;

    // Vectorized staging: one int4/float4 per thread per array.
    {
        const int i = tid * 4;
        const int e = base + i;
        if (e + 3 < n_edges) {
            int4   r = *reinterpret_cast<const int4*>(erow + e);
            int4   c = *reinterpret_cast<const int4*>(ecol + e);
            float4 v = *reinterpret_cast<const float4*>(eval + e);
            c.x *= ROW_BYTES; c.y *= ROW_BYTES; c.z *= ROW_BYTES; c.w *= ROW_BYTES;
            *reinterpret_cast<int4*>(s_row + i)   = r;
            *reinterpret_cast<int4*>(s_off + i)   = c;
            *reinterpret_cast<float4*>(s_val + i) = v;
        } else {
            // Tail: pad with last valid row, val=0 (harmless atomic of 0).
            #pragma unroll
            for (int k = 0; k < 4; k++) {
                int ee   = e + k;
                int esrc = min(ee, n_edges - 1);
                int in   = (ee < n_edges);
                s_row[i + k] = erow[esrc];
                s_off[i + k] = in ? ecol[esrc] * ROW_BYTES : 0;
                s_val[i + k] = in ? eval[esrc] : 0.f;
            }
        }
    }
    __syncthreads();

    const int d4  = tid & 15;
    const int sub = tid >> 4;
    const int off = sub * EPS;
    const char* sp = reinterpret_cast<const char*>(src + d4 * 4);

    int    cur       = s_row[off];
    int    run_start = 0;
    float4 acc       = make_float4(0.f, 0.f, 0.f, 0.f);

    for (int ib = 0; ib < EPS; ib += 8) {
        // Edge metadata: 2 LDS.128 per array (broadcast within group)
        const int4   ra = *reinterpret_cast<const int4*>(s_row + off + ib);
        const int4   rb = *reinterpret_cast<const int4*>(s_row + off + ib + 4);
        const int4   ca = *reinterpret_cast<const int4*>(s_off + off + ib);
        const int4   cb = *reinterpret_cast<const int4*>(s_off + off + ib + 4);
        const float4 va = *reinterpret_cast<const float4*>(s_val + off + ib);
        const float4 vb = *reinterpret_cast<const float4*>(s_val + off + ib + 4);

        // 8 gathers in flight (MLP = 8)
        const float4 g0 = *reinterpret_cast<const float4*>(sp + ca.x);
        const float4 g1 = *reinterpret_cast<const float4*>(sp + ca.y);
        const float4 g2 = *reinterpret_cast<const float4*>(sp + ca.z);
        const float4 g3 = *reinterpret_cast<const float4*>(sp + ca.w);
        const float4 g4 = *reinterpret_cast<const float4*>(sp + cb.x);
        const float4 g5 = *reinterpret_cast<const float4*>(sp + cb.y);
        const float4 g6 = *reinterpret_cast<const float4*>(sp + cb.z);
        const float4 g7 = *reinterpret_cast<const float4*>(sp + cb.w);

        #define STEP(R, V, G, IDX)                                           \
        do {                                                                 \
            if ((R) != cur) {                                                \
                float* p = dst + (size_t)cur * D_FEAT + d4 * 4;              \
                if (run_start > 0) {                                         \
                    *reinterpret_cast<float4*>(p) = acc;   /* exclusive */   \
                } else {                                                     \
                    red_add_v4(p, acc);                                      \
                }                                                            \
                acc = make_float4(0.f, 0.f, 0.f, 0.f);                       \
                cur = (R);                                                   \
                run_start = (IDX);                                           \
            }                                                                \
            acc.x += (V) * (G).x;                                            \
            acc.y += (V) * (G).y;                                            \
            acc.z += (V) * (G).z;                                            \
            acc.w += (V) * (G).w;                                            \
        } while (0)

        STEP(ra.x, va.x, g0, ib + 0);
        STEP(ra.y, va.y, g1, ib + 1);
        STEP(ra.z, va.z, g2, ib + 2);
        STEP(ra.w, va.w, g3, ib + 3);
        STEP(rb.x, vb.x, g4, ib + 4);
        STEP(rb.y, vb.y, g5, ib + 5);
        STEP(rb.z, vb.z, g6, ib + 6);
        STEP(rb.w, vb.w, g7, ib + 7);
        #undef STEP
    }

    // Final run may continue into the next group -> always atomic.
    red_add_v4(dst + (size_t)cur * D_FEAT + d4 * 4, acc);
}

extern "C" void kernel_launch(void* const* d_in, const int* in_sizes, int n_in,
                              void* d_out, int out_size) {
    const float* x    = (const float*)d_in[0];
    const int*   erow = (const int*)  d_in[1];
    const int*   ecol = (const int*)  d_in[2];
    const float* eval = (const float*)d_in[3];
    float*       out  = (float*)d_out;

    const int n_edges = in_sizes[1];
    const int n4      = out_size / 4;

    void* tmp_sym = nullptr;
    cudaGetSymbolAddress(&tmp_sym, g_tmp);
    float* tmp = (float*)tmp_sym;

    const int zgrid = (n4 + 255) / 256;
    const int sgrid = (n_edges + EPB - 1) / EPB;

    // Zero both buffers up front (out is only written by hop 2).
    zero2_kernel<<<zgrid, 256>>>((float4*)tmp, (float4*)out, n4);

    // Hop 1: tmp = A @ x
    spmm_kernel<<<sgrid, THREADS>>>(x, erow, ecol, eval, tmp, n_edges);
    // Hop 2: out = A @ tmp
    spmm_kernel<<<sgrid, THREADS>>>(tmp, erow, ecol, eval, out, n_edges);
}